// round 15
// baseline (speedup 1.0000x reference)
#include <cuda_runtime.h>
#include <cuda_fp16.h>
#include <math.h>
#include <cstdint>

#define Bb 4
#define Nn 2048
#define Dd 768
#define Hh 12
#define DH 64
#define M_TOT (Bb*Nn)      /* 8192 */
#define BH (Bb*Hh)         /* 48   */

// ---------------- scratch (device globals; no allocs allowed) ----------------
__device__ __half g_xn  [(size_t)M_TOT * Dd];
__device__ __half g_qkh [(size_t)M_TOT * 2 * Dd];   // QK intermediate [m][1536]
__device__ __half g_q   [(size_t)BH * Nn * DH];
__device__ __half g_k   [(size_t)BH * Nn * DH];
__device__ __half g_v   [(size_t)Dd * M_TOT];       // V TRANSPOSED: [h*64+d][b*2048+n]
__device__ __half g_ao  [(size_t)M_TOT * Dd];
__device__ __half g_wq  [(size_t)3 * Dd * Dd];
__device__ __half g_wo  [(size_t)Dd * Dd];

// ======================= helpers =======================
__device__ __forceinline__ uint32_t smem_u32(const void* p) {
    uint32_t a;
    asm("{ .reg .u64 t; cvta.to.shared.u64 t, %1; cvt.u32.u64 %0, t; }" : "=r"(a) : "l"(p));
    return a;
}
__device__ __forceinline__ void cp16(uint32_t dst, const void* src) {
    asm volatile("cp.async.cg.shared.global [%0], [%1], 16;" :: "r"(dst), "l"(src) : "memory");
}
__device__ __forceinline__ uint32_t h2(float a, float b) {
    __half2 h = __floats2half2_rn(a, b);
    return *(uint32_t*)&h;
}
// packed exp2: returns f16x2 {lo=exp2(lo), hi=exp2(hi)}
__device__ __forceinline__ uint32_t exp2_f16x2(float lo, float hi) {
    uint32_t r;
    asm("{ .reg .b32 t; cvt.rn.f16x2.f32 t, %1, %2; ex2.approx.f16x2 %0, t; }"
        : "=r"(r) : "f"(hi), "f"(lo));
    return r;
}
__device__ __forceinline__ void mma_f16(float* c, uint32_t a0, uint32_t a1, uint32_t a2, uint32_t a3,
                                        uint32_t b0, uint32_t b1) {
    asm volatile("mma.sync.aligned.m16n8k16.row.col.f32.f16.f16.f32 "
                 "{%0,%1,%2,%3}, {%4,%5,%6,%7}, {%8,%9}, {%0,%1,%2,%3};"
                 : "+f"(c[0]), "+f"(c[1]), "+f"(c[2]), "+f"(c[3])
                 : "r"(a0), "r"(a1), "r"(a2), "r"(a3), "r"(b0), "r"(b1));
}

// ---------------- fp16 conversion pass: both weight arrays, one launch ----------------
__global__ __launch_bounds__(256) void cvtw_kernel(const float* __restrict__ src1,
                                                   __half* __restrict__ dst1, int n1,
                                                   const float* __restrict__ src2,
                                                   __half* __restrict__ dst2)
{
    const int i = (blockIdx.x * 256 + threadIdx.x) * 8;
    const float* src = (i < n1) ? src1 : src2;
    __half* dst      = (i < n1) ? dst1 : dst2;
    const int off    = (i < n1) ? i : (i - n1);
    float4 v1 = *(const float4*)&src[off];
    float4 v2 = *(const float4*)&src[off + 4];
    uint4 w = make_uint4(h2(v1.x, v1.y), h2(v1.z, v1.w), h2(v2.x, v2.y), h2(v2.z, v2.w));
    *(uint4*)&dst[off] = w;
}

// ---------------- LayerNorm: warp-per-row, shfl-only reduction ----------------
__global__ __launch_bounds__(256) void ln_kernel(const float* __restrict__ x,
                                                 const float* __restrict__ gamma,
                                                 const float* __restrict__ beta,
                                                 __half* __restrict__ xn)
{
    const int lane = threadIdx.x & 31;
    const int row  = blockIdx.x * 8 + (threadIdx.x >> 5);
    const float* xr = x + (size_t)row * Dd;

    float4 v[6];
    float s = 0.f, sq = 0.f;
    #pragma unroll
    for (int i = 0; i < 6; i++) {
        v[i] = *(const float4*)&xr[i * 128 + lane * 4];
        s  += (v[i].x + v[i].y) + (v[i].z + v[i].w);
        sq += (v[i].x * v[i].x + v[i].y * v[i].y) + (v[i].z * v[i].z + v[i].w * v[i].w);
    }
    #pragma unroll
    for (int off = 16; off; off >>= 1) {
        s  += __shfl_xor_sync(0xffffffffu, s,  off);
        sq += __shfl_xor_sync(0xffffffffu, sq, off);
    }
    const float mu   = s * (1.0f / 768.0f);
    const float var  = sq * (1.0f / 768.0f) - mu * mu;
    const float rstd = rsqrtf(var + 1e-5f);

    __half* xo = xn + (size_t)row * Dd;
    #pragma unroll
    for (int i = 0; i < 6; i++) {
        const int c = i * 128 + lane * 4;
        float4 g  = *(const float4*)&gamma[c];
        float4 bb = *(const float4*)&beta[c];
        uint2 w;
        w.x = h2((v[i].x - mu) * rstd * g.x + bb.x, (v[i].y - mu) * rstd * g.y + bb.y);
        w.y = h2((v[i].z - mu) * rstd * g.z + bb.z, (v[i].w - mu) * rstd * g.w + bb.w);
        *(uint2*)&xo[c] = w;
    }
}

// ---------------- fp16 m16n8k16 GEMM: C[m,n] = sum_k A[m,k]*W[n,k] ----------------
// 128x128 CTA tile, K chunk 32, 4 warps (64x64 warp tiles), 3-stage cp.async ring.
// HALF_OUT: write C as fp16; else fp32.
#define AS_H 32                 /* halves per smem row */
#define TILE_H (128 * AS_H)     /* halves per tile (8 KB) */
template<bool HALF_OUT>
__global__ __launch_bounds__(128, 2) void gemm_mma(const __half* __restrict__ A,
                                                   const __half* __restrict__ W,
                                                   void* __restrict__ Cv,
                                                   int Np, int K)
{
    extern __shared__ __align__(16) __half sh[];
    const int tid  = threadIdx.x;
    const int lane = tid & 31;
    const int wid  = tid >> 5;
    const int wm   = wid >> 1;
    const int wn   = wid & 1;
    const int gq   = lane >> 2;
    const int jq   = lane & 3;
    const int bm   = blockIdx.y * 128;
    const int bn   = blockIdx.x * 128;

    float acc[4][8][4];
    #pragma unroll
    for (int i = 0; i < 4; i++)
        #pragma unroll
        for (int j = 0; j < 8; j++)
            #pragma unroll
            for (int q = 0; q < 4; q++) acc[i][j][q] = 0.f;

    const int nCh = K / 32;

#define LOAD_STAGE(IT, S) do {                                                  \
    const __half* Ab = A + (size_t)bm * K + (IT) * 32;                          \
    const __half* Wb = W + (size_t)bn * K + (IT) * 32;                          \
    __half* As_ = sh + (S) * (2 * TILE_H);                                      \
    __half* Bs_ = As_ + TILE_H;                                                 \
    _Pragma("unroll")                                                           \
    for (int p = 0; p < 4; p++) {                                               \
        const int idx = tid + p * 128;                                          \
        const int row = idx >> 2;                                               \
        const int c8  = (idx & 3) * 8;                                          \
        cp16(smem_u32(&As_[row * AS_H + c8]), &Ab[(size_t)row * K + c8]);       \
        cp16(smem_u32(&Bs_[row * AS_H + c8]), &Wb[(size_t)row * K + c8]);       \
    }                                                                           \
    asm volatile("cp.async.commit_group;" ::: "memory");                        \
} while (0)

    LOAD_STAGE(0, 0);
    LOAD_STAGE(1, 1);

    int s = 0, s2 = 2;
    for (int it = 0; it < nCh; it++) {
        if (it + 1 < nCh) {
            asm volatile("cp.async.wait_group 1;" ::: "memory");
        } else {
            asm volatile("cp.async.wait_group 0;" ::: "memory");
        }
        __syncthreads();
        if (it + 2 < nCh) LOAD_STAGE(it + 2, s2);

        const __half* As_ = sh + s * (2 * TILE_H);
        const __half* Bs_ = As_ + TILE_H;

        uint4 afr[8];
        #pragma unroll
        for (int mf = 0; mf < 4; mf++) {
            const int m = wm * 64 + mf * 16 + gq;
            afr[2 * mf]     = *(const uint4*)&As_[m * AS_H + 8 * jq];
            afr[2 * mf + 1] = *(const uint4*)&As_[(m + 8) * AS_H + 8 * jq];
        }
        #pragma unroll
        for (int ng = 0; ng < 2; ng++) {
            uint4 bfr[4];
            #pragma unroll
            for (int j = 0; j < 4; j++) {
                const int n = wn * 64 + (ng * 4 + j) * 8 + gq;
                bfr[j] = *(const uint4*)&Bs_[n * AS_H + 8 * jq];
            }
            #pragma unroll
            for (int mf = 0; mf < 4; mf++) {
                #pragma unroll
                for (int j = 0; j < 4; j++) {
                    float* a = acc[mf][ng * 4 + j];
                    mma_f16(a, afr[2*mf].x, afr[2*mf+1].x, afr[2*mf].y, afr[2*mf+1].y,
                            bfr[j].x, bfr[j].y);
                    mma_f16(a, afr[2*mf].z, afr[2*mf+1].z, afr[2*mf].w, afr[2*mf+1].w,
                            bfr[j].z, bfr[j].w);
                }
            }
        }
        s  = (s  == 2) ? 0 : s + 1;
        s2 = (s2 == 2) ? 0 : s2 + 1;
    }

    #pragma unroll
    for (int mf = 0; mf < 4; mf++) {
        const int r = bm + wm * 64 + mf * 16 + gq;
        #pragma unroll
        for (int nf = 0; nf < 8; nf++) {
            const int n0 = bn + wn * 64 + nf * 8 + 2 * jq;
            if (HALF_OUT) {
                __half* C = (__half*)Cv;
                *(uint32_t*)&C[(size_t)r * Np + n0]       = h2(acc[mf][nf][0], acc[mf][nf][1]);
                *(uint32_t*)&C[(size_t)(r + 8) * Np + n0] = h2(acc[mf][nf][2], acc[mf][nf][3]);
            } else {
                float* C = (float*)Cv;
                *(float2*)&C[(size_t)r * Np + n0]       = make_float2(acc[mf][nf][0], acc[mf][nf][1]);
                *(float2*)&C[(size_t)(r + 8) * Np + n0] = make_float2(acc[mf][nf][2], acc[mf][nf][3]);
            }
        }
    }
#undef LOAD_STAGE
}

// ---------------- RoPE + head split, Q/K (fp16 in/out, vectorized) ----------------
// qk: [m][1536]. 32 distinct angles/token in smem. Q scaled by 0.125*log2(e).
// task idx = which*192 + h*16 + slice*8 + isodd*4 + jg : one uint4 load, one uint2 store.
__global__ __launch_bounds__(256) void rope_kernel(const __half* __restrict__ qk,
                                                   const float* __restrict__ coords,
                                                   __half* __restrict__ Qo,
                                                   __half* __restrict__ Ko)
{
    __shared__ float cs_s[32], sn_s[32];
    const int m = blockIdx.x;
    const int b = m >> 11;
    const int n = m & 2047;
    const __half* src = qk + (size_t)m * (2 * Dd);

    if (threadIdx.x < 32) {
        const int slice = threadIdx.x >> 4;
        const int j     = threadIdx.x & 15;
        const float coord = coords[m * 2 + slice];
        const float invf  = exp2f(-13.0f * (float)j * (1.0f / 16.0f));
        float sn, cs;
        sincosf(coord * invf, &sn, &cs);
        cs_s[threadIdx.x] = cs;
        sn_s[threadIdx.x] = sn;
    }
    __syncthreads();

    #pragma unroll
    for (int p = 0; p < 2; p++) {
        const int idx = threadIdx.x + p * 256;   // 0..511, use 0..383
        if (idx >= 384) break;
        const int jg    = idx & 3;
        const int isodd = (idx >> 2) & 1;
        const int slice = (idx >> 3) & 1;
        const int h     = (idx >> 4) & 15;        // 0..11 (idx<384 -> h<12 per which)
        const int which = idx / 192;
        const int hh    = (idx - which * 192) >> 4;   // exact h 0..11

        uint4 qv = *(const uint4*)&src[which * Dd + hh * 64 + slice * 32 + 8 * jg];
        const __half2* pv = (const __half2*)&qv;
        const float qs = (which == 0) ? 0.18033688011112042f : 1.0f;  // 0.125*log2(e)
        uint32_t outp[2];
        #pragma unroll
        for (int u2 = 0; u2 < 2; u2++) {
            float vals[2];
            #pragma unroll
            for (int w = 0; w < 2; w++) {
                const int u = u2 * 2 + w;
                const int j = 4 * jg + u;
                float2 tv = __half22float2(pv[u]);
                const float cs = cs_s[slice * 16 + j];
                const float sn = sn_s[slice * 16 + j];
                float val = isodd ? (tv.x * sn + tv.y * cs) : (tv.x * cs - tv.y * sn);
                vals[w] = val * qs;
            }
            outp[u2] = h2(vals[0], vals[1]);
        }
        __half* dst = (which == 0) ? Qo : Ko;
        const size_t base = ((size_t)(b * Hh + hh) * Nn + n) * DH + slice * 32 + isodd * 16 + 4 * jg;
        *(uint2*)&dst[base] = make_uint2(outp[0], outp[1]);
    }
}

// ---------------- fp16 m16n8k16 flash attention ----------------
// Bq=128, Bk=64, 256 threads (8 warps x 16 q-rows). Q in registers, P in registers.
// 2-stage cp.async KV ring. Packed ex2.approx.f16x2 softmax.
// VT layout: [h*64+d][b*2048+n] (row stride M_TOT).
#define KSTRH 96
#define VSTRH 72
#define KVSTG_H (64 * KSTRH + 64 * VSTRH)   /* halves per stage */
__global__ __launch_bounds__(256, 2) void attn_mma(const __half* __restrict__ Q,
                                                   const __half* __restrict__ K,
                                                   const __half* __restrict__ VT,
                                                   __half* __restrict__ AO)
{
    extern __shared__ __align__(16) __half sa[];   // 2 stages x (K tile | V tile)

    const int tid  = threadIdx.x;
    const int lane = tid & 31;
    const int wid  = tid >> 5;             // 0..7
    const int gq   = lane >> 2;
    const int jq   = lane & 3;
    const int m0   = wid * 16;
    const int bh   = blockIdx.y;
    const int q0   = blockIdx.x * 128;
    const int b    = bh / Hh;
    const int h    = bh - b * Hh;

    const __half* Qbh  = Q  + (size_t)bh * Nn * DH;
    const __half* Kbh  = K  + (size_t)bh * Nn * DH;
    const __half* VTbh = VT + (size_t)(h * DH) * M_TOT + (size_t)b * Nn;

    // Q A-fragments (loaded once): chunk c covers d in [32c, 32c+32)
    uint4 qa[2][2];
    #pragma unroll
    for (int c = 0; c < 2; c++) {
        qa[c][0] = *(const uint4*)&Qbh[(size_t)(q0 + m0 + gq) * DH + c * 32 + 8 * jq];
        qa[c][1] = *(const uint4*)&Qbh[(size_t)(q0 + m0 + gq + 8) * DH + c * 32 + 8 * jq];
    }

    float o[8][4];
    #pragma unroll
    for (int t = 0; t < 8; t++)
        #pragma unroll
        for (int j = 0; j < 4; j++) o[t][j] = 0.f;
    float m_lo = -1e30f, m_hi = -1e30f, l_lo = 0.f, l_hi = 0.f;

#define PREFETCH(IT, S) do {                                                        \
    __half* Kd = sa + (S) * KVSTG_H;                                                \
    __half* Vd = Kd + 64 * KSTRH;                                                   \
    _Pragma("unroll")                                                               \
    for (int p = 0; p < 2; p++) {                                                   \
        const int idx = tid + p * 256;                                              \
        const int row = idx >> 3;                                                   \
        const int c8  = (idx & 7) * 8;                                              \
        cp16(smem_u32(&Kd[row * KSTRH + c8]), &Kbh[(size_t)((IT) * 64 + row) * DH + c8]);     \
        cp16(smem_u32(&Vd[row * VSTRH + c8]), &VTbh[(size_t)row * M_TOT + (IT) * 64 + c8]);   \
    }                                                                               \
    asm volatile("cp.async.commit_group;" ::: "memory");                            \
} while (0)

    PREFETCH(0, 0);

    const int nT = Nn / 64;
    for (int it = 0; it < nT; it++) {
        const int s = it & 1;
        asm volatile("cp.async.wait_group 0;" ::: "memory");
        __syncthreads();
        if (it + 1 < nT) PREFETCH(it + 1, s ^ 1);

        const __half* Ksm = sa + s * KVSTG_H;
        const __half* Vsm = Ksm + 64 * KSTRH;

        // ---- S = Q K^T ----
        float sc[8][4];
        #pragma unroll
        for (int t = 0; t < 8; t++)
            #pragma unroll
            for (int j = 0; j < 4; j++) sc[t][j] = 0.f;

        #pragma unroll
        for (int c = 0; c < 2; c++) {
            const uint4 a0 = qa[c][0], a1 = qa[c][1];
            #pragma unroll
            for (int t = 0; t < 8; t++) {
                uint4 kv = *(const uint4*)&Ksm[(t * 8 + gq) * KSTRH + c * 32 + 8 * jq];
                mma_f16(sc[t], a0.x, a1.x, a0.y, a1.y, kv.x, kv.y);
                mma_f16(sc[t], a0.z, a1.z, a0.w, a1.w, kv.z, kv.w);
            }
        }

        // ---- online softmax (log2 domain); rows gq -> c0,c1 ; gq+8 -> c2,c3 ----
        float smax_lo = -1e30f, smax_hi = -1e30f;
        #pragma unroll
        for (int t = 0; t < 8; t++) {
            smax_lo = fmaxf(smax_lo, fmaxf(sc[t][0], sc[t][1]));
            smax_hi = fmaxf(smax_hi, fmaxf(sc[t][2], sc[t][3]));
        }
        #pragma unroll
        for (int off = 1; off <= 2; off <<= 1) {
            smax_lo = fmaxf(smax_lo, __shfl_xor_sync(0xffffffffu, smax_lo, off));
            smax_hi = fmaxf(smax_hi, __shfl_xor_sync(0xffffffffu, smax_hi, off));
        }
        const float mn_lo = fmaxf(m_lo, smax_lo);
        const float mn_hi = fmaxf(m_hi, smax_hi);
        const float cr_lo = exp2f(m_lo - mn_lo);
        const float cr_hi = exp2f(m_hi - mn_hi);
        m_lo = mn_lo; m_hi = mn_hi;

        // packed fp16 P, fp32 row-sum of exactly those fp16 values
        uint32_t p01[8], p23[8];
        float ls_lo = 0.f, ls_hi = 0.f;
        #pragma unroll
        for (int t = 0; t < 8; t++) {
            p01[t] = exp2_f16x2(sc[t][0] - mn_lo, sc[t][1] - mn_lo);
            p23[t] = exp2_f16x2(sc[t][2] - mn_hi, sc[t][3] - mn_hi);
            float2 f0 = __half22float2(*(const __half2*)&p01[t]);
            float2 f1 = __half22float2(*(const __half2*)&p23[t]);
            ls_lo += f0.x + f0.y;
            ls_hi += f1.x + f1.y;
        }
        #pragma unroll
        for (int off = 1; off <= 2; off <<= 1) {
            ls_lo += __shfl_xor_sync(0xffffffffu, ls_lo, off);
            ls_hi += __shfl_xor_sync(0xffffffffu, ls_hi, off);
        }
        l_lo = l_lo * cr_lo + ls_lo;
        l_hi = l_hi * cr_hi + ls_hi;
        #pragma unroll
        for (int t = 0; t < 8; t++) {
            o[t][0] *= cr_lo; o[t][1] *= cr_lo;
            o[t][2] *= cr_hi; o[t][3] *= cr_hi;
        }

        // ---- O += P V : packed P IS the fp16 A-frag ----
        #pragma unroll
        for (int c = 0; c < 4; c++) {
            const uint32_t a0 = p01[2 * c];
            const uint32_t a1 = p23[2 * c];
            const uint32_t a2 = p01[2 * c + 1];
            const uint32_t a3 = p23[2 * c + 1];
            #pragma unroll
            for (int t = 0; t < 8; t++) {
                const uint32_t b0 = *(const uint32_t*)&Vsm[(t * 8 + gq) * VSTRH + c * 16 + 2 * jq];
                const uint32_t b1 = *(const uint32_t*)&Vsm[(t * 8 + gq) * VSTRH + c * 16 + 8 + 2 * jq];
                mma_f16(o[t], a0, a1, a2, a3, b0, b1);
            }
        }
    }
#undef PREFETCH

    // epilogue: normalize, write fp16 AO[b][n][h*64+d]
    const float inv_lo = 1.0f / l_lo;
    const float inv_hi = 1.0f / l_hi;
    #pragma unroll
    for (int t = 0; t < 8; t++) {
        const int col = h * DH + t * 8 + 2 * jq;
        const size_t r0 = (size_t)(b * Nn + q0 + m0 + gq) * Dd + col;
        const size_t r1 = (size_t)(b * Nn + q0 + m0 + gq + 8) * Dd + col;
        *(uint32_t*)&AO[r0] = h2(o[t][0] * inv_lo, o[t][1] * inv_lo);
        *(uint32_t*)&AO[r1] = h2(o[t][2] * inv_hi, o[t][3] * inv_hi);
    }
}

// ---------------- launch ----------------
extern "C" void kernel_launch(void* const* d_in, const int* in_sizes, int n_in,
                              void* d_out, int out_size)
{
    const float* x      = (const float*)d_in[0];
    const float* coords = (const float*)d_in[1];
    const float* gamma  = (const float*)d_in[2];
    const float* beta   = (const float*)d_in[3];
    const float* wqkv   = (const float*)d_in[4];
    const float* wout   = (const float*)d_in[5];
    float* out = (float*)d_out;

    __half *xn, *qkh, *q, *k, *v, *ao, *wq, *wo;
    cudaGetSymbolAddress((void**)&xn,  g_xn);
    cudaGetSymbolAddress((void**)&qkh, g_qkh);
    cudaGetSymbolAddress((void**)&q,   g_q);
    cudaGetSymbolAddress((void**)&k,   g_k);
    cudaGetSymbolAddress((void**)&v,   g_v);
    cudaGetSymbolAddress((void**)&ao,  g_ao);
    cudaGetSymbolAddress((void**)&wq,  g_wq);
    cudaGetSymbolAddress((void**)&wo,  g_wo);

    const int gemm_smem = 3 * 2 * TILE_H * (int)sizeof(__half);   // 49152 B
    const int attn_smem = 2 * KVSTG_H * (int)sizeof(__half);      // 43008 B
    cudaFuncSetAttribute(gemm_mma<true>,  cudaFuncAttributeMaxDynamicSharedMemorySize, gemm_smem);
    cudaFuncSetAttribute(gemm_mma<false>, cudaFuncAttributeMaxDynamicSharedMemorySize, gemm_smem);
    cudaFuncSetAttribute(attn_mma, cudaFuncAttributeMaxDynamicSharedMemorySize, attn_smem);

    const int nwq = 3 * Dd * Dd, nwo = Dd * Dd;
    cvtw_kernel<<<(nwq + nwo) / 2048, 256>>>(wqkv, wq, nwq, wout, wo);
    ln_kernel<<<M_TOT / 8, 256>>>(x, gamma, beta, xn);
    // QK GEMM: [8192 tokens] x [1536 qk-dims]
    gemm_mma<true><<<dim3(2 * Dd / 128, M_TOT / 128), 128, gemm_smem>>>(xn, wq, qkh, 2 * Dd, Dd);
    // V GEMM, transposed output: C[dglobal][token]  (A = w_v rows, B = xn rows)
    gemm_mma<true><<<dim3(M_TOT / 128, Dd / 128), 128, gemm_smem>>>(wq + (size_t)2 * Dd * Dd, xn, v, M_TOT, Dd);
    rope_kernel<<<M_TOT, 256>>>(qkh, coords, q, k);
    attn_mma<<<dim3(Nn / 128, BH), 256, attn_smem>>>(q, k, v, ao);
    gemm_mma<false><<<dim3(Dd / 128, M_TOT / 128), 128, gemm_smem>>>(ao, wo, out, Dd, Dd);
}

// round 16
// speedup vs baseline: 1.0327x; 1.0327x over previous
#include <cuda_runtime.h>
#include <cuda_fp16.h>
#include <math.h>
#include <cstdint>

#define Bb 4
#define Nn 2048
#define Dd 768
#define Hh 12
#define DH 64
#define M_TOT (Bb*Nn)      /* 8192 */
#define BH (Bb*Hh)         /* 48   */

// ---------------- scratch (device globals; no allocs allowed) ----------------
__device__ __half g_xn  [(size_t)M_TOT * Dd];
__device__ __half g_qkvh[(size_t)M_TOT * 3 * Dd];
__device__ __half g_q   [(size_t)BH * Nn * DH];
__device__ __half g_k   [(size_t)BH * Nn * DH];
__device__ __half g_v   [(size_t)BH * Nn * DH];   // TRANSPOSED: [bh][d][n]
__device__ __half g_ao  [(size_t)M_TOT * Dd];
__device__ __half g_wq  [(size_t)3 * Dd * Dd];
__device__ __half g_wo  [(size_t)Dd * Dd];

// ======================= helpers =======================
__device__ __forceinline__ uint32_t smem_u32(const void* p) {
    uint32_t a;
    asm("{ .reg .u64 t; cvta.to.shared.u64 t, %1; cvt.u32.u64 %0, t; }" : "=r"(a) : "l"(p));
    return a;
}
__device__ __forceinline__ void cp16(uint32_t dst, const void* src) {
    asm volatile("cp.async.cg.shared.global [%0], [%1], 16;" :: "r"(dst), "l"(src) : "memory");
}
__device__ __forceinline__ uint32_t h2(float a, float b) {
    __half2 h = __floats2half2_rn(a, b);
    return *(uint32_t*)&h;
}
// packed exp2: returns f16x2 {lo=exp2(lo), hi=exp2(hi)}
__device__ __forceinline__ uint32_t exp2_f16x2(float lo, float hi) {
    uint32_t r;
    asm("{ .reg .b32 t; cvt.rn.f16x2.f32 t, %1, %2; ex2.approx.f16x2 %0, t; }"
        : "=r"(r) : "f"(hi), "f"(lo));
    return r;
}
__device__ __forceinline__ void mma_f16(float* c, uint32_t a0, uint32_t a1, uint32_t a2, uint32_t a3,
                                        uint32_t b0, uint32_t b1) {
    asm volatile("mma.sync.aligned.m16n8k16.row.col.f32.f16.f16.f32 "
                 "{%0,%1,%2,%3}, {%4,%5,%6,%7}, {%8,%9}, {%0,%1,%2,%3};"
                 : "+f"(c[0]), "+f"(c[1]), "+f"(c[2]), "+f"(c[3])
                 : "r"(a0), "r"(a1), "r"(a2), "r"(a3), "r"(b0), "r"(b1));
}

// ---------------- fp16 conversion pass: both weight arrays, one launch ----------------
__global__ __launch_bounds__(256) void cvtw_kernel(const float* __restrict__ src1,
                                                   __half* __restrict__ dst1, int n1,
                                                   const float* __restrict__ src2,
                                                   __half* __restrict__ dst2)
{
    const int i = (blockIdx.x * 256 + threadIdx.x) * 8;
    const float* src = (i < n1) ? src1 : src2;
    __half* dst      = (i < n1) ? dst1 : dst2;
    const int off    = (i < n1) ? i : (i - n1);
    float4 v1 = *(const float4*)&src[off];
    float4 v2 = *(const float4*)&src[off + 4];
    uint4 w = make_uint4(h2(v1.x, v1.y), h2(v1.z, v1.w), h2(v2.x, v2.y), h2(v2.z, v2.w));
    *(uint4*)&dst[off] = w;
}

// ---------------- LayerNorm: warp-per-row, shfl-only reduction ----------------
__global__ __launch_bounds__(256) void ln_kernel(const float* __restrict__ x,
                                                 const float* __restrict__ gamma,
                                                 const float* __restrict__ beta,
                                                 __half* __restrict__ xn)
{
    const int lane = threadIdx.x & 31;
    const int row  = blockIdx.x * 8 + (threadIdx.x >> 5);
    const float* xr = x + (size_t)row * Dd;

    float4 v[6];
    float s = 0.f, sq = 0.f;
    #pragma unroll
    for (int i = 0; i < 6; i++) {
        v[i] = *(const float4*)&xr[i * 128 + lane * 4];
        s  += (v[i].x + v[i].y) + (v[i].z + v[i].w);
        sq += (v[i].x * v[i].x + v[i].y * v[i].y) + (v[i].z * v[i].z + v[i].w * v[i].w);
    }
    #pragma unroll
    for (int off = 16; off; off >>= 1) {
        s  += __shfl_xor_sync(0xffffffffu, s,  off);
        sq += __shfl_xor_sync(0xffffffffu, sq, off);
    }
    const float mu   = s * (1.0f / 768.0f);
    const float var  = sq * (1.0f / 768.0f) - mu * mu;
    const float rstd = rsqrtf(var + 1e-5f);

    __half* xo = xn + (size_t)row * Dd;
    #pragma unroll
    for (int i = 0; i < 6; i++) {
        const int c = i * 128 + lane * 4;
        float4 g  = *(const float4*)&gamma[c];
        float4 bb = *(const float4*)&beta[c];
        uint2 w;
        w.x = h2((v[i].x - mu) * rstd * g.x + bb.x, (v[i].y - mu) * rstd * g.y + bb.y);
        w.y = h2((v[i].z - mu) * rstd * g.z + bb.z, (v[i].w - mu) * rstd * g.w + bb.w);
        *(uint2*)&xo[c] = w;
    }
}

// ---------------- fp16 m16n8k16 GEMM: C[m,n] = sum_k A[m,k]*W[n,k] ----------------
// 128x128 CTA tile, K chunk 32, 4 warps (64x64 warp tiles), 3-stage cp.async ring.
// HALF_OUT: write C as fp16 (for the qkv intermediate); else fp32.
#define AS_H 32                 /* halves per smem row */
#define TILE_H (128 * AS_H)     /* halves per tile (8 KB) */
template<bool HALF_OUT>
__global__ __launch_bounds__(128, 2) void gemm_mma(const __half* __restrict__ A,
                                                   const __half* __restrict__ W,
                                                   void* __restrict__ Cv,
                                                   int Np, int K)
{
    extern __shared__ __align__(16) __half sh[];
    const int tid  = threadIdx.x;
    const int lane = tid & 31;
    const int wid  = tid >> 5;
    const int wm   = wid >> 1;
    const int wn   = wid & 1;
    const int gq   = lane >> 2;
    const int jq   = lane & 3;
    const int bm   = blockIdx.y * 128;
    const int bn   = blockIdx.x * 128;

    float acc[4][8][4];
    #pragma unroll
    for (int i = 0; i < 4; i++)
        #pragma unroll
        for (int j = 0; j < 8; j++)
            #pragma unroll
            for (int q = 0; q < 4; q++) acc[i][j][q] = 0.f;

    const int nCh = K / 32;

#define LOAD_STAGE(IT, S) do {                                                  \
    const __half* Ab = A + (size_t)bm * K + (IT) * 32;                          \
    const __half* Wb = W + (size_t)bn * K + (IT) * 32;                          \
    __half* As_ = sh + (S) * (2 * TILE_H);                                      \
    __half* Bs_ = As_ + TILE_H;                                                 \
    _Pragma("unroll")                                                           \
    for (int p = 0; p < 4; p++) {                                               \
        const int idx = tid + p * 128;                                          \
        const int row = idx >> 2;                                               \
        const int c8  = (idx & 3) * 8;                                          \
        cp16(smem_u32(&As_[row * AS_H + c8]), &Ab[(size_t)row * K + c8]);       \
        cp16(smem_u32(&Bs_[row * AS_H + c8]), &Wb[(size_t)row * K + c8]);       \
    }                                                                           \
    asm volatile("cp.async.commit_group;" ::: "memory");                        \
} while (0)

    LOAD_STAGE(0, 0);
    LOAD_STAGE(1, 1);

    int s = 0, s2 = 2;
    for (int it = 0; it < nCh; it++) {
        if (it + 1 < nCh) {
            asm volatile("cp.async.wait_group 1;" ::: "memory");
        } else {
            asm volatile("cp.async.wait_group 0;" ::: "memory");
        }
        __syncthreads();
        if (it + 2 < nCh) LOAD_STAGE(it + 2, s2);

        const __half* As_ = sh + s * (2 * TILE_H);
        const __half* Bs_ = As_ + TILE_H;

        uint4 afr[8];
        #pragma unroll
        for (int mf = 0; mf < 4; mf++) {
            const int m = wm * 64 + mf * 16 + gq;
            afr[2 * mf]     = *(const uint4*)&As_[m * AS_H + 8 * jq];
            afr[2 * mf + 1] = *(const uint4*)&As_[(m + 8) * AS_H + 8 * jq];
        }
        #pragma unroll
        for (int ng = 0; ng < 2; ng++) {
            uint4 bfr[4];
            #pragma unroll
            for (int j = 0; j < 4; j++) {
                const int n = wn * 64 + (ng * 4 + j) * 8 + gq;
                bfr[j] = *(const uint4*)&Bs_[n * AS_H + 8 * jq];
            }
            #pragma unroll
            for (int mf = 0; mf < 4; mf++) {
                #pragma unroll
                for (int j = 0; j < 4; j++) {
                    float* a = acc[mf][ng * 4 + j];
                    mma_f16(a, afr[2*mf].x, afr[2*mf+1].x, afr[2*mf].y, afr[2*mf+1].y,
                            bfr[j].x, bfr[j].y);
                    mma_f16(a, afr[2*mf].z, afr[2*mf+1].z, afr[2*mf].w, afr[2*mf+1].w,
                            bfr[j].z, bfr[j].w);
                }
            }
        }
        s  = (s  == 2) ? 0 : s + 1;
        s2 = (s2 == 2) ? 0 : s2 + 1;
    }

    #pragma unroll
    for (int mf = 0; mf < 4; mf++) {
        const int r = bm + wm * 64 + mf * 16 + gq;
        #pragma unroll
        for (int nf = 0; nf < 8; nf++) {
            const int n0 = bn + wn * 64 + nf * 8 + 2 * jq;
            if (HALF_OUT) {
                __half* C = (__half*)Cv;
                *(uint32_t*)&C[(size_t)r * Np + n0]       = h2(acc[mf][nf][0], acc[mf][nf][1]);
                *(uint32_t*)&C[(size_t)(r + 8) * Np + n0] = h2(acc[mf][nf][2], acc[mf][nf][3]);
            } else {
                float* C = (float*)Cv;
                *(float2*)&C[(size_t)r * Np + n0]       = make_float2(acc[mf][nf][0], acc[mf][nf][1]);
                *(float2*)&C[(size_t)(r + 8) * Np + n0] = make_float2(acc[mf][nf][2], acc[mf][nf][3]);
            }
        }
    }
#undef LOAD_STAGE
}

// ---------------- RoPE + head split, Q/K (fp16 in/out, vectorized) ----------------
// qkv: [m][2304]. 32 distinct angles/token in smem. Q scaled by 0.125*log2(e).
// task idx < 384: one uint4 load (4 pairs), one uint2 store (4 halves).
__global__ __launch_bounds__(256) void rope_kernel(const __half* __restrict__ qkv,
                                                   const float* __restrict__ coords,
                                                   __half* __restrict__ Qo,
                                                   __half* __restrict__ Ko)
{
    __shared__ float cs_s[32], sn_s[32];
    const int m = blockIdx.x;
    const int b = m >> 11;
    const int n = m & 2047;
    const __half* src = qkv + (size_t)m * (3 * Dd);

    if (threadIdx.x < 32) {
        const int slice = threadIdx.x >> 4;
        const int j     = threadIdx.x & 15;
        const float coord = coords[m * 2 + slice];
        const float invf  = exp2f(-13.0f * (float)j * (1.0f / 16.0f));
        float sn, cs;
        sincosf(coord * invf, &sn, &cs);
        cs_s[threadIdx.x] = cs;
        sn_s[threadIdx.x] = sn;
    }
    __syncthreads();

    #pragma unroll
    for (int p = 0; p < 2; p++) {
        const int idx = threadIdx.x + p * 256;   // 0..511, use 0..383
        if (idx >= 384) break;
        const int jg    = idx & 3;
        const int isodd = (idx >> 2) & 1;
        const int slice = (idx >> 3) & 1;
        const int which = idx / 192;
        const int hh    = (idx - which * 192) >> 4;   // 0..11

        uint4 qv = *(const uint4*)&src[which * Dd + hh * 64 + slice * 32 + 8 * jg];
        const __half2* pv = (const __half2*)&qv;
        const float qs = (which == 0) ? 0.18033688011112042f : 1.0f;  // 0.125*log2(e)
        uint32_t outp[2];
        #pragma unroll
        for (int u2 = 0; u2 < 2; u2++) {
            float vals[2];
            #pragma unroll
            for (int w = 0; w < 2; w++) {
                const int u = u2 * 2 + w;
                const int j = 4 * jg + u;
                float2 tv = __half22float2(pv[u]);
                const float cs = cs_s[slice * 16 + j];
                const float sn = sn_s[slice * 16 + j];
                float val = isodd ? (tv.x * sn + tv.y * cs) : (tv.x * cs - tv.y * sn);
                vals[w] = val * qs;
            }
            outp[u2] = h2(vals[0], vals[1]);
        }
        __half* dst = (which == 0) ? Qo : Ko;
        const size_t base = ((size_t)(b * Hh + hh) * Nn + n) * DH + slice * 32 + isodd * 16 + 4 * jg;
        *(uint2*)&dst[base] = make_uint2(outp[0], outp[1]);
    }
}

// ---------------- V transpose: qkv V-part [m][d] (fp16) -> VT [bh][d][n] ----------------
__global__ __launch_bounds__(256) void vt_kernel(const __half* __restrict__ qkv,
                                                 __half* __restrict__ Vo)
{
    __shared__ float tile[64][65];
    const int n0  = blockIdx.x * 64;
    const int bh  = blockIdx.y;
    const int b   = bh / Hh;
    const int h   = bh - b * Hh;
    const int tid = threadIdx.x;

    #pragma unroll
    for (int p = 0; p < 2; p++) {
        const int idx = tid + p * 256;          // 0..511
        const int i   = idx >> 3;               // token 0..63
        const int d8  = (idx & 7) * 8;
        const __half* src = qkv + (size_t)(b * Nn + n0 + i) * (3 * Dd) + 2 * Dd + h * 64 + d8;
        uint4 v = *(const uint4*)src;
        const __half2* hv = (const __half2*)&v;
        #pragma unroll
        for (int u = 0; u < 4; u++) {
            float2 f = __half22float2(hv[u]);
            tile[d8 + 2 * u][i]     = f.x;
            tile[d8 + 2 * u + 1][i] = f.y;
        }
    }
    __syncthreads();

    #pragma unroll
    for (int p = 0; p < 2; p++) {
        const int idx = tid + p * 256;          // 0..511
        const int d   = idx >> 3;               // 0..63
        const int j8  = (idx & 7) * 8;
        uint4 w;
        w.x = h2(tile[d][j8 + 0], tile[d][j8 + 1]);
        w.y = h2(tile[d][j8 + 2], tile[d][j8 + 3]);
        w.z = h2(tile[d][j8 + 4], tile[d][j8 + 5]);
        w.w = h2(tile[d][j8 + 6], tile[d][j8 + 7]);
        *(uint4*)&Vo[((size_t)bh * DH + d) * Nn + n0 + j8] = w;
    }
}

// ---------------- fp16 m16n8k16 flash attention ----------------
// Bq=128, Bk=64, 256 threads (8 warps x 16 q-rows). Q in registers, P in registers.
// 2-stage cp.async KV ring. Packed ex2.approx.f16x2 softmax.
#define KSTRH 96
#define VSTRH 72
#define KVSTG_H (64 * KSTRH + 64 * VSTRH)   /* halves per stage */
__global__ __launch_bounds__(256, 2) void attn_mma(const __half* __restrict__ Q,
                                                   const __half* __restrict__ K,
                                                   const __half* __restrict__ VT,
                                                   __half* __restrict__ AO)
{
    extern __shared__ __align__(16) __half sa[];   // 2 stages x (K tile | V tile)

    const int tid  = threadIdx.x;
    const int lane = tid & 31;
    const int wid  = tid >> 5;             // 0..7
    const int gq   = lane >> 2;
    const int jq   = lane & 3;
    const int m0   = wid * 16;
    const int bh   = blockIdx.y;
    const int q0   = blockIdx.x * 128;
    const int b    = bh / Hh;
    const int h    = bh - b * Hh;

    const __half* Qbh  = Q  + (size_t)bh * Nn * DH;
    const __half* Kbh  = K  + (size_t)bh * Nn * DH;
    const __half* VTbh = VT + (size_t)bh * DH * Nn;

    // Q A-fragments (loaded once): chunk c covers d in [32c, 32c+32)
    uint4 qa[2][2];
    #pragma unroll
    for (int c = 0; c < 2; c++) {
        qa[c][0] = *(const uint4*)&Qbh[(size_t)(q0 + m0 + gq) * DH + c * 32 + 8 * jq];
        qa[c][1] = *(const uint4*)&Qbh[(size_t)(q0 + m0 + gq + 8) * DH + c * 32 + 8 * jq];
    }

    float o[8][4];
    #pragma unroll
    for (int t = 0; t < 8; t++)
        #pragma unroll
        for (int j = 0; j < 4; j++) o[t][j] = 0.f;
    float m_lo = -1e30f, m_hi = -1e30f, l_lo = 0.f, l_hi = 0.f;

#define PREFETCH(IT, S) do {                                                        \
    __half* Kd = sa + (S) * KVSTG_H;                                                \
    __half* Vd = Kd + 64 * KSTRH;                                                   \
    _Pragma("unroll")                                                               \
    for (int p = 0; p < 2; p++) {                                                   \
        const int idx = tid + p * 256;                                              \
        const int row = idx >> 3;                                                   \
        const int c8  = (idx & 7) * 8;                                              \
        cp16(smem_u32(&Kd[row * KSTRH + c8]), &Kbh[(size_t)((IT) * 64 + row) * DH + c8]); \
        cp16(smem_u32(&Vd[row * VSTRH + c8]), &VTbh[(size_t)row * Nn + (IT) * 64 + c8]);  \
    }                                                                               \
    asm volatile("cp.async.commit_group;" ::: "memory");                            \
} while (0)

    PREFETCH(0, 0);

    const int nT = Nn / 64;
    for (int it = 0; it < nT; it++) {
        const int s = it & 1;
        asm volatile("cp.async.wait_group 0;" ::: "memory");
        __syncthreads();
        if (it + 1 < nT) PREFETCH(it + 1, s ^ 1);

        const __half* Ksm = sa + s * KVSTG_H;
        const __half* Vsm = Ksm + 64 * KSTRH;

        // ---- S = Q K^T ----
        float sc[8][4];
        #pragma unroll
        for (int t = 0; t < 8; t++)
            #pragma unroll
            for (int j = 0; j < 4; j++) sc[t][j] = 0.f;

        #pragma unroll
        for (int c = 0; c < 2; c++) {
            const uint4 a0 = qa[c][0], a1 = qa[c][1];
            #pragma unroll
            for (int t = 0; t < 8; t++) {
                uint4 kv = *(const uint4*)&Ksm[(t * 8 + gq) * KSTRH + c * 32 + 8 * jq];
                mma_f16(sc[t], a0.x, a1.x, a0.y, a1.y, kv.x, kv.y);
                mma_f16(sc[t], a0.z, a1.z, a0.w, a1.w, kv.z, kv.w);
            }
        }

        // ---- online softmax (log2 domain); rows gq -> c0,c1 ; gq+8 -> c2,c3 ----
        float smax_lo = -1e30f, smax_hi = -1e30f;
        #pragma unroll
        for (int t = 0; t < 8; t++) {
            smax_lo = fmaxf(smax_lo, fmaxf(sc[t][0], sc[t][1]));
            smax_hi = fmaxf(smax_hi, fmaxf(sc[t][2], sc[t][3]));
        }
        #pragma unroll
        for (int off = 1; off <= 2; off <<= 1) {
            smax_lo = fmaxf(smax_lo, __shfl_xor_sync(0xffffffffu, smax_lo, off));
            smax_hi = fmaxf(smax_hi, __shfl_xor_sync(0xffffffffu, smax_hi, off));
        }
        const float mn_lo = fmaxf(m_lo, smax_lo);
        const float mn_hi = fmaxf(m_hi, smax_hi);
        const float cr_lo = exp2f(m_lo - mn_lo);
        const float cr_hi = exp2f(m_hi - mn_hi);
        m_lo = mn_lo; m_hi = mn_hi;

        // packed fp16 P, fp32 row-sum of exactly those fp16 values
        uint32_t p01[8], p23[8];
        float ls_lo = 0.f, ls_hi = 0.f;
        #pragma unroll
        for (int t = 0; t < 8; t++) {
            p01[t] = exp2_f16x2(sc[t][0] - mn_lo, sc[t][1] - mn_lo);
            p23[t] = exp2_f16x2(sc[t][2] - mn_hi, sc[t][3] - mn_hi);
            float2 f0 = __half22float2(*(const __half2*)&p01[t]);
            float2 f1 = __half22float2(*(const __half2*)&p23[t]);
            ls_lo += f0.x + f0.y;
            ls_hi += f1.x + f1.y;
        }
        #pragma unroll
        for (int off = 1; off <= 2; off <<= 1) {
            ls_lo += __shfl_xor_sync(0xffffffffu, ls_lo, off);
            ls_hi += __shfl_xor_sync(0xffffffffu, ls_hi, off);
        }
        l_lo = l_lo * cr_lo + ls_lo;
        l_hi = l_hi * cr_hi + ls_hi;
        #pragma unroll
        for (int t = 0; t < 8; t++) {
            o[t][0] *= cr_lo; o[t][1] *= cr_lo;
            o[t][2] *= cr_hi; o[t][3] *= cr_hi;
        }

        // ---- O += P V : packed P IS the fp16 A-frag ----
        #pragma unroll
        for (int c = 0; c < 4; c++) {
            const uint32_t a0 = p01[2 * c];
            const uint32_t a1 = p23[2 * c];
            const uint32_t a2 = p01[2 * c + 1];
            const uint32_t a3 = p23[2 * c + 1];
            #pragma unroll
            for (int t = 0; t < 8; t++) {
                const uint32_t b0 = *(const uint32_t*)&Vsm[(t * 8 + gq) * VSTRH + c * 16 + 2 * jq];
                const uint32_t b1 = *(const uint32_t*)&Vsm[(t * 8 + gq) * VSTRH + c * 16 + 8 + 2 * jq];
                mma_f16(o[t], a0, a1, a2, a3, b0, b1);
            }
        }
    }
#undef PREFETCH

    // epilogue: normalize, write fp16 AO[b][n][h*64+d]
    const float inv_lo = 1.0f / l_lo;
    const float inv_hi = 1.0f / l_hi;
    #pragma unroll
    for (int t = 0; t < 8; t++) {
        const int col = h * DH + t * 8 + 2 * jq;
        const size_t r0 = (size_t)(b * Nn + q0 + m0 + gq) * Dd + col;
        const size_t r1 = (size_t)(b * Nn + q0 + m0 + gq + 8) * Dd + col;
        *(uint32_t*)&AO[r0] = h2(o[t][0] * inv_lo, o[t][1] * inv_lo);
        *(uint32_t*)&AO[r1] = h2(o[t][2] * inv_hi, o[t][3] * inv_hi);
    }
}

// ---------------- launch ----------------
extern "C" void kernel_launch(void* const* d_in, const int* in_sizes, int n_in,
                              void* d_out, int out_size)
{
    const float* x      = (const float*)d_in[0];
    const float* coords = (const float*)d_in[1];
    const float* gamma  = (const float*)d_in[2];
    const float* beta   = (const float*)d_in[3];
    const float* wqkv   = (const float*)d_in[4];
    const float* wout   = (const float*)d_in[5];
    float* out = (float*)d_out;

    __half *xn, *qkvh, *q, *k, *v, *ao, *wq, *wo;
    cudaGetSymbolAddress((void**)&xn,   g_xn);
    cudaGetSymbolAddress((void**)&qkvh, g_qkvh);
    cudaGetSymbolAddress((void**)&q,    g_q);
    cudaGetSymbolAddress((void**)&k,    g_k);
    cudaGetSymbolAddress((void**)&v,    g_v);
    cudaGetSymbolAddress((void**)&ao,   g_ao);
    cudaGetSymbolAddress((void**)&wq,   g_wq);
    cudaGetSymbolAddress((void**)&wo,   g_wo);

    const int gemm_smem = 3 * 2 * TILE_H * (int)sizeof(__half);   // 49152 B
    const int attn_smem = 2 * KVSTG_H * (int)sizeof(__half);      // 43008 B
    cudaFuncSetAttribute(gemm_mma<true>,  cudaFuncAttributeMaxDynamicSharedMemorySize, gemm_smem);
    cudaFuncSetAttribute(gemm_mma<false>, cudaFuncAttributeMaxDynamicSharedMemorySize, gemm_smem);
    cudaFuncSetAttribute(attn_mma, cudaFuncAttributeMaxDynamicSharedMemorySize, attn_smem);

    const int nwq = 3 * Dd * Dd, nwo = Dd * Dd;
    cvtw_kernel<<<(nwq + nwo) / 2048, 256>>>(wqkv, wq, nwq, wout, wo);
    ln_kernel<<<M_TOT / 8, 256>>>(x, gamma, beta, xn);
    gemm_mma<true><<<dim3(3 * Dd / 128, M_TOT / 128), 128, gemm_smem>>>(xn, wq, qkvh, 3 * Dd, Dd);
    rope_kernel<<<M_TOT, 256>>>(qkvh, coords, q, k);
    vt_kernel<<<dim3(Nn / 64, BH), 256>>>(qkvh, v);
    attn_mma<<<dim3(Nn / 128, BH), 256, attn_smem>>>(q, k, v, ao);
    gemm_mma<false><<<dim3(Dd / 128, M_TOT / 128), 128, gemm_smem>>>(ao, wo, out, Dd, Dd);
}

// round 17
// speedup vs baseline: 1.0404x; 1.0075x over previous
#include <cuda_runtime.h>
#include <cuda_fp16.h>
#include <math.h>
#include <cstdint>

#define Bb 4
#define Nn 2048
#define Dd 768
#define Hh 12
#define DH 64
#define M_TOT (Bb*Nn)      /* 8192 */
#define BH (Bb*Hh)         /* 48   */

// ---------------- scratch (device globals; no allocs allowed) ----------------
__device__ __half g_xn  [(size_t)M_TOT * Dd];
__device__ __half g_qkvh[(size_t)M_TOT * 3 * Dd];
__device__ __half g_q   [(size_t)BH * Nn * DH];
__device__ __half g_k   [(size_t)BH * Nn * DH];
__device__ __half g_v   [(size_t)BH * Nn * DH];   // TRANSPOSED: [bh][d][n]
__device__ __half g_ao  [(size_t)M_TOT * Dd];
__device__ __half g_wq  [(size_t)3 * Dd * Dd];
__device__ __half g_wo  [(size_t)Dd * Dd];

// ======================= helpers =======================
__device__ __forceinline__ uint32_t smem_u32(const void* p) {
    uint32_t a;
    asm("{ .reg .u64 t; cvta.to.shared.u64 t, %1; cvt.u32.u64 %0, t; }" : "=r"(a) : "l"(p));
    return a;
}
__device__ __forceinline__ void cp16(uint32_t dst, const void* src) {
    asm volatile("cp.async.cg.shared.global [%0], [%1], 16;" :: "r"(dst), "l"(src) : "memory");
}
__device__ __forceinline__ uint32_t h2(float a, float b) {
    __half2 h = __floats2half2_rn(a, b);
    return *(uint32_t*)&h;
}
// packed exp2: returns f16x2 {lo=exp2(lo), hi=exp2(hi)}
__device__ __forceinline__ uint32_t exp2_f16x2(float lo, float hi) {
    uint32_t r;
    asm("{ .reg .b32 t; cvt.rn.f16x2.f32 t, %1, %2; ex2.approx.f16x2 %0, t; }"
        : "=r"(r) : "f"(hi), "f"(lo));
    return r;
}
__device__ __forceinline__ void mma_f16(float* c, uint32_t a0, uint32_t a1, uint32_t a2, uint32_t a3,
                                        uint32_t b0, uint32_t b1) {
    asm volatile("mma.sync.aligned.m16n8k16.row.col.f32.f16.f16.f32 "
                 "{%0,%1,%2,%3}, {%4,%5,%6,%7}, {%8,%9}, {%0,%1,%2,%3};"
                 : "+f"(c[0]), "+f"(c[1]), "+f"(c[2]), "+f"(c[3])
                 : "r"(a0), "r"(a1), "r"(a2), "r"(a3), "r"(b0), "r"(b1));
}

// ---------------- fused LayerNorm + weight-conversion ----------------
// blocks [0, M_TOT/8): warp-per-row LN.  blocks [M_TOT/8, +2304): cvt weights.
__global__ __launch_bounds__(256) void ln_cvtw_kernel(const float* __restrict__ x,
                                                      const float* __restrict__ gamma,
                                                      const float* __restrict__ beta,
                                                      __half* __restrict__ xn,
                                                      const float* __restrict__ wsrc1,
                                                      __half* __restrict__ wdst1, int n1,
                                                      const float* __restrict__ wsrc2,
                                                      __half* __restrict__ wdst2)
{
    if (blockIdx.x < M_TOT / 8) {
        const int lane = threadIdx.x & 31;
        const int row  = blockIdx.x * 8 + (threadIdx.x >> 5);
        const float* xr = x + (size_t)row * Dd;

        float4 v[6];
        float s = 0.f, sq = 0.f;
        #pragma unroll
        for (int i = 0; i < 6; i++) {
            v[i] = *(const float4*)&xr[i * 128 + lane * 4];
            s  += (v[i].x + v[i].y) + (v[i].z + v[i].w);
            sq += (v[i].x * v[i].x + v[i].y * v[i].y) + (v[i].z * v[i].z + v[i].w * v[i].w);
        }
        #pragma unroll
        for (int off = 16; off; off >>= 1) {
            s  += __shfl_xor_sync(0xffffffffu, s,  off);
            sq += __shfl_xor_sync(0xffffffffu, sq, off);
        }
        const float mu   = s * (1.0f / 768.0f);
        const float var  = sq * (1.0f / 768.0f) - mu * mu;
        const float rstd = rsqrtf(var + 1e-5f);

        __half* xo = xn + (size_t)row * Dd;
        #pragma unroll
        for (int i = 0; i < 6; i++) {
            const int c = i * 128 + lane * 4;
            float4 g  = *(const float4*)&gamma[c];
            float4 bb = *(const float4*)&beta[c];
            uint2 w;
            w.x = h2((v[i].x - mu) * rstd * g.x + bb.x, (v[i].y - mu) * rstd * g.y + bb.y);
            w.y = h2((v[i].z - mu) * rstd * g.z + bb.z, (v[i].w - mu) * rstd * g.w + bb.w);
            *(uint2*)&xo[c] = w;
        }
    } else {
        const int i = ((blockIdx.x - M_TOT / 8) * 256 + threadIdx.x) * 8;
        const float* src = (i < n1) ? wsrc1 : wsrc2;
        __half* dst      = (i < n1) ? wdst1 : wdst2;
        const int off    = (i < n1) ? i : (i - n1);
        float4 v1 = *(const float4*)&src[off];
        float4 v2 = *(const float4*)&src[off + 4];
        uint4 w = make_uint4(h2(v1.x, v1.y), h2(v1.z, v1.w), h2(v2.x, v2.y), h2(v2.z, v2.w));
        *(uint4*)&dst[off] = w;
    }
}

// ---------------- fp16 m16n8k16 GEMM: C[m,n] = sum_k A[m,k]*W[n,k] ----------------
// 128x128 CTA tile, K chunk 32, 4 warps (64x64 warp tiles), 3-stage cp.async ring.
// HALF_OUT: write C as fp16 (for the qkv intermediate); else fp32.
#define AS_H 32                 /* halves per smem row */
#define TILE_H (128 * AS_H)     /* halves per tile (8 KB) */
template<bool HALF_OUT>
__global__ __launch_bounds__(128, 2) void gemm_mma(const __half* __restrict__ A,
                                                   const __half* __restrict__ W,
                                                   void* __restrict__ Cv,
                                                   int Np, int K)
{
    extern __shared__ __align__(16) __half sh[];
    const int tid  = threadIdx.x;
    const int lane = tid & 31;
    const int wid  = tid >> 5;
    const int wm   = wid >> 1;
    const int wn   = wid & 1;
    const int gq   = lane >> 2;
    const int jq   = lane & 3;
    const int bm   = blockIdx.y * 128;
    const int bn   = blockIdx.x * 128;

    float acc[4][8][4];
    #pragma unroll
    for (int i = 0; i < 4; i++)
        #pragma unroll
        for (int j = 0; j < 8; j++)
            #pragma unroll
            for (int q = 0; q < 4; q++) acc[i][j][q] = 0.f;

    const int nCh = K / 32;

#define LOAD_STAGE(IT, S) do {                                                  \
    const __half* Ab = A + (size_t)bm * K + (IT) * 32;                          \
    const __half* Wb = W + (size_t)bn * K + (IT) * 32;                          \
    __half* As_ = sh + (S) * (2 * TILE_H);                                      \
    __half* Bs_ = As_ + TILE_H;                                                 \
    _Pragma("unroll")                                                           \
    for (int p = 0; p < 4; p++) {                                               \
        const int idx = tid + p * 128;                                          \
        const int row = idx >> 2;                                               \
        const int c8  = (idx & 3) * 8;                                          \
        cp16(smem_u32(&As_[row * AS_H + c8]), &Ab[(size_t)row * K + c8]);       \
        cp16(smem_u32(&Bs_[row * AS_H + c8]), &Wb[(size_t)row * K + c8]);       \
    }                                                                           \
    asm volatile("cp.async.commit_group;" ::: "memory");                        \
} while (0)

    LOAD_STAGE(0, 0);
    LOAD_STAGE(1, 1);

    int s = 0, s2 = 2;
    for (int it = 0; it < nCh; it++) {
        if (it + 1 < nCh) {
            asm volatile("cp.async.wait_group 1;" ::: "memory");
        } else {
            asm volatile("cp.async.wait_group 0;" ::: "memory");
        }
        __syncthreads();
        if (it + 2 < nCh) LOAD_STAGE(it + 2, s2);

        const __half* As_ = sh + s * (2 * TILE_H);
        const __half* Bs_ = As_ + TILE_H;

        uint4 afr[8];
        #pragma unroll
        for (int mf = 0; mf < 4; mf++) {
            const int m = wm * 64 + mf * 16 + gq;
            afr[2 * mf]     = *(const uint4*)&As_[m * AS_H + 8 * jq];
            afr[2 * mf + 1] = *(const uint4*)&As_[(m + 8) * AS_H + 8 * jq];
        }
        #pragma unroll
        for (int ng = 0; ng < 2; ng++) {
            uint4 bfr[4];
            #pragma unroll
            for (int j = 0; j < 4; j++) {
                const int n = wn * 64 + (ng * 4 + j) * 8 + gq;
                bfr[j] = *(const uint4*)&Bs_[n * AS_H + 8 * jq];
            }
            #pragma unroll
            for (int mf = 0; mf < 4; mf++) {
                #pragma unroll
                for (int j = 0; j < 4; j++) {
                    float* a = acc[mf][ng * 4 + j];
                    mma_f16(a, afr[2*mf].x, afr[2*mf+1].x, afr[2*mf].y, afr[2*mf+1].y,
                            bfr[j].x, bfr[j].y);
                    mma_f16(a, afr[2*mf].z, afr[2*mf+1].z, afr[2*mf].w, afr[2*mf+1].w,
                            bfr[j].z, bfr[j].w);
                }
            }
        }
        s  = (s  == 2) ? 0 : s + 1;
        s2 = (s2 == 2) ? 0 : s2 + 1;
    }

    #pragma unroll
    for (int mf = 0; mf < 4; mf++) {
        const int r = bm + wm * 64 + mf * 16 + gq;
        #pragma unroll
        for (int nf = 0; nf < 8; nf++) {
            const int n0 = bn + wn * 64 + nf * 8 + 2 * jq;
            if (HALF_OUT) {
                __half* C = (__half*)Cv;
                *(uint32_t*)&C[(size_t)r * Np + n0]       = h2(acc[mf][nf][0], acc[mf][nf][1]);
                *(uint32_t*)&C[(size_t)(r + 8) * Np + n0] = h2(acc[mf][nf][2], acc[mf][nf][3]);
            } else {
                float* C = (float*)Cv;
                *(float2*)&C[(size_t)r * Np + n0]       = make_float2(acc[mf][nf][0], acc[mf][nf][1]);
                *(float2*)&C[(size_t)(r + 8) * Np + n0] = make_float2(acc[mf][nf][2], acc[mf][nf][3]);
            }
        }
    }
#undef LOAD_STAGE
}

// ---------------- fused RoPE (Q/K) + V transpose ----------------
// blocks [0, M_TOT): scalar rope per token (R14 form, measured best).
// blocks [M_TOT, +BH*Nn/64): smem-tiled V transpose.
__global__ __launch_bounds__(256) void rope_vt_kernel(const __half* __restrict__ qkv,
                                                      const float* __restrict__ coords,
                                                      __half* __restrict__ Qo,
                                                      __half* __restrict__ Ko,
                                                      __half* __restrict__ Vo)
{
    __shared__ float tile[64][65];        // vt branch
    __shared__ float cs_s[32], sn_s[32];  // rope branch

    if (blockIdx.x < M_TOT) {
        const int m = blockIdx.x;
        const int b = m >> 11;
        const int n = m & 2047;
        const __half* src = qkv + (size_t)m * (3 * Dd);

        if (threadIdx.x < 32) {
            const int slice = threadIdx.x >> 4;
            const int j     = threadIdx.x & 15;
            const float coord = coords[m * 2 + slice];
            const float invf  = exp2f(-13.0f * (float)j * (1.0f / 16.0f));
            float sn, cs;
            sincosf(coord * invf, &sn, &cs);
            cs_s[threadIdx.x] = cs;
            sn_s[threadIdx.x] = sn;
        }
        __syncthreads();

        #pragma unroll
        for (int p = 0; p < 6; p++) {
            const int t = threadIdx.x + p * 256;   // 0..1535
            const int which = t / Dd;              // 0=q 1=k
            const int r     = t - which * Dd;
            const int h     = r >> 6;
            const int d     = r & 63;
            const int slice = d >> 5;
            const int dl    = d & 31;
            const int j     = dl & 15;
            const int isodd = dl >> 4;
            const float cs = cs_s[slice * 16 + j];
            const float sn = sn_s[slice * 16 + j];
            const int   e  = which * Dd + h * 64 + slice * 32 + 2 * j;
            float2 tv = __half22float2(*(const __half2*)&src[e]);
            float val = isodd ? (tv.x * sn + tv.y * cs) : (tv.x * cs - tv.y * sn);
            if (which == 0) val *= 0.18033688011112042f;   // 0.125 * log2(e)
            __half* dst = (which == 0) ? Qo : Ko;
            dst[((size_t)(b * Hh + h) * Nn + n) * DH + d] = __float2half_rn(val);
        }
    } else {
        const int vb  = blockIdx.x - M_TOT;
        const int n0  = (vb & 31) * 64;           // 32 n-chunks
        const int bh  = vb >> 5;
        const int b   = bh / Hh;
        const int h   = bh - b * Hh;
        const int tid = threadIdx.x;

        #pragma unroll
        for (int p = 0; p < 2; p++) {
            const int idx = tid + p * 256;          // 0..511
            const int i   = idx >> 3;               // token 0..63
            const int d8  = (idx & 7) * 8;
            const __half* src = qkv + (size_t)(b * Nn + n0 + i) * (3 * Dd) + 2 * Dd + h * 64 + d8;
            uint4 v = *(const uint4*)src;
            const __half2* hv = (const __half2*)&v;
            #pragma unroll
            for (int u = 0; u < 4; u++) {
                float2 f = __half22float2(hv[u]);
                tile[d8 + 2 * u][i]     = f.x;
                tile[d8 + 2 * u + 1][i] = f.y;
            }
        }
        __syncthreads();

        #pragma unroll
        for (int p = 0; p < 2; p++) {
            const int idx = tid + p * 256;          // 0..511
            const int d   = idx >> 3;               // 0..63
            const int j8  = (idx & 7) * 8;
            uint4 w;
            w.x = h2(tile[d][j8 + 0], tile[d][j8 + 1]);
            w.y = h2(tile[d][j8 + 2], tile[d][j8 + 3]);
            w.z = h2(tile[d][j8 + 4], tile[d][j8 + 5]);
            w.w = h2(tile[d][j8 + 6], tile[d][j8 + 7]);
            *(uint4*)&Vo[((size_t)bh * DH + d) * Nn + n0 + j8] = w;
        }
    }
}

// ---------------- fp16 m16n8k16 flash attention ----------------
// Bq=128, Bk=64, 256 threads (8 warps x 16 q-rows). Q in registers, P in registers.
// 2-stage cp.async KV ring. Packed ex2.approx.f16x2 softmax.
#define KSTRH 96
#define VSTRH 72
#define KVSTG_H (64 * KSTRH + 64 * VSTRH)   /* halves per stage */
__global__ __launch_bounds__(256, 2) void attn_mma(const __half* __restrict__ Q,
                                                   const __half* __restrict__ K,
                                                   const __half* __restrict__ VT,
                                                   __half* __restrict__ AO)
{
    extern __shared__ __align__(16) __half sa[];   // 2 stages x (K tile | V tile)

    const int tid  = threadIdx.x;
    const int lane = tid & 31;
    const int wid  = tid >> 5;             // 0..7
    const int gq   = lane >> 2;
    const int jq   = lane & 3;
    const int m0   = wid * 16;
    const int bh   = blockIdx.y;
    const int q0   = blockIdx.x * 128;
    const int b    = bh / Hh;
    const int h    = bh - b * Hh;

    const __half* Qbh  = Q  + (size_t)bh * Nn * DH;
    const __half* Kbh  = K  + (size_t)bh * Nn * DH;
    const __half* VTbh = VT + (size_t)bh * DH * Nn;

    // Q A-fragments (loaded once): chunk c covers d in [32c, 32c+32)
    uint4 qa[2][2];
    #pragma unroll
    for (int c = 0; c < 2; c++) {
        qa[c][0] = *(const uint4*)&Qbh[(size_t)(q0 + m0 + gq) * DH + c * 32 + 8 * jq];
        qa[c][1] = *(const uint4*)&Qbh[(size_t)(q0 + m0 + gq + 8) * DH + c * 32 + 8 * jq];
    }

    float o[8][4];
    #pragma unroll
    for (int t = 0; t < 8; t++)
        #pragma unroll
        for (int j = 0; j < 4; j++) o[t][j] = 0.f;
    float m_lo = -1e30f, m_hi = -1e30f, l_lo = 0.f, l_hi = 0.f;

#define PREFETCH(IT, S) do {                                                        \
    __half* Kd = sa + (S) * KVSTG_H;                                                \
    __half* Vd = Kd + 64 * KSTRH;                                                   \
    _Pragma("unroll")                                                               \
    for (int p = 0; p < 2; p++) {                                                   \
        const int idx = tid + p * 256;                                              \
        const int row = idx >> 3;                                                   \
        const int c8  = (idx & 7) * 8;                                              \
        cp16(smem_u32(&Kd[row * KSTRH + c8]), &Kbh[(size_t)((IT) * 64 + row) * DH + c8]); \
        cp16(smem_u32(&Vd[row * VSTRH + c8]), &VTbh[(size_t)row * Nn + (IT) * 64 + c8]);  \
    }                                                                               \
    asm volatile("cp.async.commit_group;" ::: "memory");                            \
} while (0)

    PREFETCH(0, 0);

    const int nT = Nn / 64;
    for (int it = 0; it < nT; it++) {
        const int s = it & 1;
        asm volatile("cp.async.wait_group 0;" ::: "memory");
        __syncthreads();
        if (it + 1 < nT) PREFETCH(it + 1, s ^ 1);

        const __half* Ksm = sa + s * KVSTG_H;
        const __half* Vsm = Ksm + 64 * KSTRH;

        // ---- S = Q K^T ----
        float sc[8][4];
        #pragma unroll
        for (int t = 0; t < 8; t++)
            #pragma unroll
            for (int j = 0; j < 4; j++) sc[t][j] = 0.f;

        #pragma unroll
        for (int c = 0; c < 2; c++) {
            const uint4 a0 = qa[c][0], a1 = qa[c][1];
            #pragma unroll
            for (int t = 0; t < 8; t++) {
                uint4 kv = *(const uint4*)&Ksm[(t * 8 + gq) * KSTRH + c * 32 + 8 * jq];
                mma_f16(sc[t], a0.x, a1.x, a0.y, a1.y, kv.x, kv.y);
                mma_f16(sc[t], a0.z, a1.z, a0.w, a1.w, kv.z, kv.w);
            }
        }

        // ---- online softmax (log2 domain); rows gq -> c0,c1 ; gq+8 -> c2,c3 ----
        float smax_lo = -1e30f, smax_hi = -1e30f;
        #pragma unroll
        for (int t = 0; t < 8; t++) {
            smax_lo = fmaxf(smax_lo, fmaxf(sc[t][0], sc[t][1]));
            smax_hi = fmaxf(smax_hi, fmaxf(sc[t][2], sc[t][3]));
        }
        #pragma unroll
        for (int off = 1; off <= 2; off <<= 1) {
            smax_lo = fmaxf(smax_lo, __shfl_xor_sync(0xffffffffu, smax_lo, off));
            smax_hi = fmaxf(smax_hi, __shfl_xor_sync(0xffffffffu, smax_hi, off));
        }
        const float mn_lo = fmaxf(m_lo, smax_lo);
        const float mn_hi = fmaxf(m_hi, smax_hi);
        const float cr_lo = exp2f(m_lo - mn_lo);
        const float cr_hi = exp2f(m_hi - mn_hi);
        m_lo = mn_lo; m_hi = mn_hi;

        // packed fp16 P, fp32 row-sum of exactly those fp16 values
        uint32_t p01[8], p23[8];
        float ls_lo = 0.f, ls_hi = 0.f;
        #pragma unroll
        for (int t = 0; t < 8; t++) {
            p01[t] = exp2_f16x2(sc[t][0] - mn_lo, sc[t][1] - mn_lo);
            p23[t] = exp2_f16x2(sc[t][2] - mn_hi, sc[t][3] - mn_hi);
            float2 f0 = __half22float2(*(const __half2*)&p01[t]);
            float2 f1 = __half22float2(*(const __half2*)&p23[t]);
            ls_lo += f0.x + f0.y;
            ls_hi += f1.x + f1.y;
        }
        #pragma unroll
        for (int off = 1; off <= 2; off <<= 1) {
            ls_lo += __shfl_xor_sync(0xffffffffu, ls_lo, off);
            ls_hi += __shfl_xor_sync(0xffffffffu, ls_hi, off);
        }
        l_lo = l_lo * cr_lo + ls_lo;
        l_hi = l_hi * cr_hi + ls_hi;
        #pragma unroll
        for (int t = 0; t < 8; t++) {
            o[t][0] *= cr_lo; o[t][1] *= cr_lo;
            o[t][2] *= cr_hi; o[t][3] *= cr_hi;
        }

        // ---- O += P V : packed P IS the fp16 A-frag ----
        #pragma unroll
        for (int c = 0; c < 4; c++) {
            const uint32_t a0 = p01[2 * c];
            const uint32_t a1 = p23[2 * c];
            const uint32_t a2 = p01[2 * c + 1];
            const uint32_t a3 = p23[2 * c + 1];
            #pragma unroll
            for (int t = 0; t < 8; t++) {
                const uint32_t b0 = *(const uint32_t*)&Vsm[(t * 8 + gq) * VSTRH + c * 16 + 2 * jq];
                const uint32_t b1 = *(const uint32_t*)&Vsm[(t * 8 + gq) * VSTRH + c * 16 + 8 + 2 * jq];
                mma_f16(o[t], a0, a1, a2, a3, b0, b1);
            }
        }
    }
#undef PREFETCH

    // epilogue: normalize, write fp16 AO[b][n][h*64+d]
    const float inv_lo = 1.0f / l_lo;
    const float inv_hi = 1.0f / l_hi;
    #pragma unroll
    for (int t = 0; t < 8; t++) {
        const int col = h * DH + t * 8 + 2 * jq;
        const size_t r0 = (size_t)(b * Nn + q0 + m0 + gq) * Dd + col;
        const size_t r1 = (size_t)(b * Nn + q0 + m0 + gq + 8) * Dd + col;
        *(uint32_t*)&AO[r0] = h2(o[t][0] * inv_lo, o[t][1] * inv_lo);
        *(uint32_t*)&AO[r1] = h2(o[t][2] * inv_hi, o[t][3] * inv_hi);
    }
}

// ---------------- launch ----------------
extern "C" void kernel_launch(void* const* d_in, const int* in_sizes, int n_in,
                              void* d_out, int out_size)
{
    const float* x      = (const float*)d_in[0];
    const float* coords = (const float*)d_in[1];
    const float* gamma  = (const float*)d_in[2];
    const float* beta   = (const float*)d_in[3];
    const float* wqkv   = (const float*)d_in[4];
    const float* wout   = (const float*)d_in[5];
    float* out = (float*)d_out;

    __half *xn, *qkvh, *q, *k, *v, *ao, *wq, *wo;
    cudaGetSymbolAddress((void**)&xn,   g_xn);
    cudaGetSymbolAddress((void**)&qkvh, g_qkvh);
    cudaGetSymbolAddress((void**)&q,    g_q);
    cudaGetSymbolAddress((void**)&k,    g_k);
    cudaGetSymbolAddress((void**)&v,    g_v);
    cudaGetSymbolAddress((void**)&ao,   g_ao);
    cudaGetSymbolAddress((void**)&wq,   g_wq);
    cudaGetSymbolAddress((void**)&wo,   g_wo);

    const int gemm_smem = 3 * 2 * TILE_H * (int)sizeof(__half);   // 49152 B
    const int attn_smem = 2 * KVSTG_H * (int)sizeof(__half);      // 43008 B
    cudaFuncSetAttribute(gemm_mma<true>,  cudaFuncAttributeMaxDynamicSharedMemorySize, gemm_smem);
    cudaFuncSetAttribute(gemm_mma<false>, cudaFuncAttributeMaxDynamicSharedMemorySize, gemm_smem);
    cudaFuncSetAttribute(attn_mma, cudaFuncAttributeMaxDynamicSharedMemorySize, attn_smem);

    const int nwq = 3 * Dd * Dd, nwo = Dd * Dd;
    const int cvt_blocks = (nwq + nwo) / 2048;                    // 2304
    ln_cvtw_kernel<<<M_TOT / 8 + cvt_blocks, 256>>>(x, gamma, beta, xn,
                                                    wqkv, wq, nwq, wout, wo);
    gemm_mma<true><<<dim3(3 * Dd / 128, M_TOT / 128), 128, gemm_smem>>>(xn, wq, qkvh, 3 * Dd, Dd);
    rope_vt_kernel<<<M_TOT + BH * (Nn / 64), 256>>>(qkvh, coords, q, k, v);
    attn_mma<<<dim3(Nn / 128, BH), 256, attn_smem>>>(q, k, v, ao);
    gemm_mma<false><<<dim3(Dd / 128, M_TOT / 128), 128, gemm_smem>>>(ao, wo, out, Dd, Dd);
}